// round 1
// baseline (speedup 1.0000x reference)
#include <cuda_runtime.h>

// ---------------------------------------------------------------------------
// ChebyKANLayer: out[n,o] = clip( sum_{i,d} T_d(tanh(clip(x[n,i]))) * coeffs[o,i,d] )
// N=16384, I=2048, O=2048, DEG=4.
//
// T0 == 1  ->  folded into a per-o bias.  Effective GEMM: [16384 x 8192] @ [8192 x 2048]^T
// |tanh| <= 1 -> Chebyshev values bounded by 1, intermediate clips are exact no-ops.
// ---------------------------------------------------------------------------

#define N_ROWS 16384
#define I_DIM  2048
#define O_DIM  2048
#define KDIM   (I_DIM * 4)   // 8192 (degrees 1..4)

__device__ __align__(16) float g_feat[(size_t)N_ROWS * KDIM];  // 512 MB scratch: A [N, K]
__device__ __align__(16) float g_B   [(size_t)O_DIM  * KDIM];  // 64 MB:  B [O, K]
__device__ float g_bias[O_DIM];

static __device__ __forceinline__ float clampf(float v, float c) {
    return fminf(fmaxf(v, -c), c);
}

// ---------------- feature map: t, T2, T3, T4 per (n,i), float4 store -------
__global__ void feat_kernel(const float* __restrict__ x) {
    int idx = blockIdx.x * blockDim.x + threadIdx.x;   // n*I + i  (< 2^25)
    if (idx >= N_ROWS * I_DIM) return;
    float v = clampf(x[idx], 10.0f);
    // tanh via expf: accurate under both default and fast-math compilation
    float e = expf(2.0f * v);
    float t  = (e - 1.0f) / (e + 1.0f);
    float t2 = 2.0f * t * t  - 1.0f;
    float t3 = 2.0f * t * t2 - t;
    float t4 = 2.0f * t * t3 - t2;
    reinterpret_cast<float4*>(g_feat)[idx] = make_float4(t, t2, t3, t4);
}

// ---------------- repack coeffs d=1..4 into B[o, i*4 + (d-1)] --------------
__global__ void repack_kernel(const float* __restrict__ coeffs) {
    int idx = blockIdx.x * blockDim.x + threadIdx.x;   // o*I + i
    if (idx >= O_DIM * I_DIM) return;
    const float* s = coeffs + (size_t)idx * 5;
    reinterpret_cast<float4*>(g_B)[idx] = make_float4(s[1], s[2], s[3], s[4]);
}

// ---------------- bias[o] = sum_i coeffs[o,i,0] -----------------------------
__global__ void bias_kernel(const float* __restrict__ coeffs) {
    int o = blockIdx.x;
    float s = 0.0f;
    for (int i = threadIdx.x; i < I_DIM; i += blockDim.x)
        s += coeffs[((size_t)o * I_DIM + i) * 5];
    __shared__ float red[256];
    red[threadIdx.x] = s;
    __syncthreads();
    for (int off = 128; off > 0; off >>= 1) {
        if (threadIdx.x < off) red[threadIdx.x] += red[threadIdx.x + off];
        __syncthreads();
    }
    if (threadIdx.x == 0) g_bias[o] = red[0];
}

// ---------------- SGEMM (NT): C[m,o] = clip(A[m,:] . B[o,:] + bias[o]) ------
#define BM 128
#define BN 128
#define BK 16
#define SMP 132   // padded row length to reduce STS bank conflicts

__global__ void __launch_bounds__(256, 2)
gemm_kernel(float* __restrict__ C) {
    __shared__ float As[2][BK][SMP];
    __shared__ float Bs[2][BK][SMP];

    const int tid   = threadIdx.x;
    const int mBase = blockIdx.y * BM;
    const int nBase = blockIdx.x * BN;

    // global-load geometry: 256 threads = 64 rows x 4 float4-columns per half
    const int lrow = tid >> 2;   // 0..63
    const int lcol = tid & 3;    // 0..3  -> k offset lcol*4
    const float* Aptr = g_feat + (size_t)(mBase + lrow) * KDIM + lcol * 4;
    const float* Bptr = g_B    + (size_t)(nBase + lrow) * KDIM + lcol * 4;

    // compute geometry: 16x16 threads, 8x8 micro-tile each
    const int tr = tid >> 4;     // 0..15 -> m
    const int tc = tid & 15;     // 0..15 -> n

    float acc[8][8];
#pragma unroll
    for (int i = 0; i < 8; ++i)
#pragma unroll
        for (int j = 0; j < 8; ++j) acc[i][j] = 0.0f;

    // prologue: fill stage 0
    {
        float4 a0 = *(const float4*)(Aptr);
        float4 a1 = *(const float4*)(Aptr + (size_t)64 * KDIM);
        float4 b0 = *(const float4*)(Bptr);
        float4 b1 = *(const float4*)(Bptr + (size_t)64 * KDIM);
        As[0][lcol*4+0][lrow]    = a0.x; As[0][lcol*4+1][lrow]    = a0.y;
        As[0][lcol*4+2][lrow]    = a0.z; As[0][lcol*4+3][lrow]    = a0.w;
        As[0][lcol*4+0][lrow+64] = a1.x; As[0][lcol*4+1][lrow+64] = a1.y;
        As[0][lcol*4+2][lrow+64] = a1.z; As[0][lcol*4+3][lrow+64] = a1.w;
        Bs[0][lcol*4+0][lrow]    = b0.x; Bs[0][lcol*4+1][lrow]    = b0.y;
        Bs[0][lcol*4+2][lrow]    = b0.z; Bs[0][lcol*4+3][lrow]    = b0.w;
        Bs[0][lcol*4+0][lrow+64] = b1.x; Bs[0][lcol*4+1][lrow+64] = b1.y;
        Bs[0][lcol*4+2][lrow+64] = b1.z; Bs[0][lcol*4+3][lrow+64] = b1.w;
    }
    __syncthreads();

    const int nK = KDIM / BK;   // 512
    float4 aR0, aR1, bR0, bR1;

    for (int kt = 0; kt < nK; ++kt) {
        const int s = kt & 1;
        if (kt + 1 < nK) {
            const float* Ap = Aptr + (size_t)(kt + 1) * BK;
            const float* Bp = Bptr + (size_t)(kt + 1) * BK;
            aR0 = *(const float4*)(Ap);
            aR1 = *(const float4*)(Ap + (size_t)64 * KDIM);
            bR0 = *(const float4*)(Bp);
            bR1 = *(const float4*)(Bp + (size_t)64 * KDIM);
        }
#pragma unroll
        for (int k = 0; k < BK; ++k) {
            float4 av0 = *(const float4*)&As[s][k][tr * 8];
            float4 av1 = *(const float4*)&As[s][k][tr * 8 + 4];
            float4 bv0 = *(const float4*)&Bs[s][k][tc * 8];
            float4 bv1 = *(const float4*)&Bs[s][k][tc * 8 + 4];
            float am[8] = {av0.x, av0.y, av0.z, av0.w, av1.x, av1.y, av1.z, av1.w};
            float bn[8] = {bv0.x, bv0.y, bv0.z, bv0.w, bv1.x, bv1.y, bv1.z, bv1.w};
#pragma unroll
            for (int i = 0; i < 8; ++i)
#pragma unroll
                for (int j = 0; j < 8; ++j)
                    acc[i][j] = fmaf(am[i], bn[j], acc[i][j]);
        }
        if (kt + 1 < nK) {
            const int s2 = s ^ 1;
            As[s2][lcol*4+0][lrow]    = aR0.x; As[s2][lcol*4+1][lrow]    = aR0.y;
            As[s2][lcol*4+2][lrow]    = aR0.z; As[s2][lcol*4+3][lrow]    = aR0.w;
            As[s2][lcol*4+0][lrow+64] = aR1.x; As[s2][lcol*4+1][lrow+64] = aR1.y;
            As[s2][lcol*4+2][lrow+64] = aR1.z; As[s2][lcol*4+3][lrow+64] = aR1.w;
            Bs[s2][lcol*4+0][lrow]    = bR0.x; Bs[s2][lcol*4+1][lrow]    = bR0.y;
            Bs[s2][lcol*4+2][lrow]    = bR0.z; Bs[s2][lcol*4+3][lrow]    = bR0.w;
            Bs[s2][lcol*4+0][lrow+64] = bR1.x; Bs[s2][lcol*4+1][lrow+64] = bR1.y;
            Bs[s2][lcol*4+2][lrow+64] = bR1.z; Bs[s2][lcol*4+3][lrow+64] = bR1.w;
        }
        __syncthreads();
    }

    // epilogue: add bias, clip, vectorized store
    float bv[8];
#pragma unroll
    for (int j = 0; j < 8; ++j) bv[j] = g_bias[nBase + tc * 8 + j];

#pragma unroll
    for (int i = 0; i < 8; ++i) {
        const int m = mBase + tr * 8 + i;
        float4 o0, o1;
        o0.x = clampf(acc[i][0] + bv[0], 10.0f);
        o0.y = clampf(acc[i][1] + bv[1], 10.0f);
        o0.z = clampf(acc[i][2] + bv[2], 10.0f);
        o0.w = clampf(acc[i][3] + bv[3], 10.0f);
        o1.x = clampf(acc[i][4] + bv[4], 10.0f);
        o1.y = clampf(acc[i][5] + bv[5], 10.0f);
        o1.z = clampf(acc[i][6] + bv[6], 10.0f);
        o1.w = clampf(acc[i][7] + bv[7], 10.0f);
        float* outp = C + (size_t)m * O_DIM + nBase + tc * 8;
        *(float4*)(outp)     = o0;
        *(float4*)(outp + 4) = o1;
    }
}

// ---------------------------------------------------------------------------
extern "C" void kernel_launch(void* const* d_in, const int* in_sizes, int n_in,
                              void* d_out, int out_size) {
    const float* x      = (const float*)d_in[0];
    const float* coeffs = (const float*)d_in[1];
    float* out          = (float*)d_out;

    feat_kernel  <<<(N_ROWS * I_DIM + 255) / 256, 256>>>(x);
    repack_kernel<<<(O_DIM  * I_DIM + 255) / 256, 256>>>(coeffs);
    bias_kernel  <<<O_DIM, 256>>>(coeffs);
    gemm_kernel  <<<dim3(O_DIM / BN, N_ROWS / BM), 256>>>(out);
}

// round 3
// speedup vs baseline: 9.2695x; 9.2695x over previous
#include <cuda_runtime.h>
#include <cuda_fp16.h>
#include <cstdint>

// ---------------------------------------------------------------------------
// ChebyKAN: out[n,o] = clip( sum_{i,d=0..4} T_d(tanh(clip(x[n,i]))) * coeffs[o,i,d] )
// N=16384, I=2048, O=2048.  T0==1 folded into bias; GEMM K = I*4 = 8192, fp16.
// Baseline-ISA tensor cores: ldmatrix + mma.sync.m16n8k16 (no tcgen05 — the
// harness compiles through compute_103 virtual arch, which rejects 'a' features).
// TMA bulk-async 3-stage pipeline from pre-swizzled tile-contiguous operands.
// ---------------------------------------------------------------------------

#define N_ROWS 16384
#define I_DIM  2048
#define O_DIM  2048
#define KDIM   8192
#define MT     128
#define NT     128
#define KC     64
#define NPAIR  (KDIM / KC)           // 128 k-chunks
#define NSTG   3
#define TILE_B 16384                 // 128 rows x 128 B (KC=64 fp16)
#define STG_B  (2 * TILE_B)          // A tile + B tile
#define SMEM_TOTAL (1024 + NSTG * STG_B)   // 99328
#define CLAMP10 10.0f

__device__ __align__(1024) unsigned char g_A[(size_t)N_ROWS * KDIM * 2]; // 256 MB
__device__ __align__(1024) unsigned char g_B[(size_t)O_DIM  * KDIM * 2]; //  32 MB
__device__ float g_bias[O_DIM];

static __device__ __forceinline__ uint32_t swz128(uint32_t off) {
    return off ^ ((off >> 3) & 0x70);
}
static __device__ __forceinline__ float clampf(float v) {
    return fminf(fmaxf(v, -CLAMP10), CLAMP10);
}
static __device__ __forceinline__ uint32_t smem_u32(const void* p) {
    return (uint32_t)__cvta_generic_to_shared(p);
}
static __device__ __forceinline__ void mbar_init(uint32_t a, uint32_t cnt) {
    asm volatile("mbarrier.init.shared.b64 [%0], %1;" :: "r"(a), "r"(cnt) : "memory");
}
static __device__ __forceinline__ void mbar_expect_tx(uint32_t a, uint32_t bytes) {
    asm volatile("mbarrier.arrive.expect_tx.shared.b64 _, [%0], %1;" :: "r"(a), "r"(bytes) : "memory");
}
static __device__ __forceinline__ void mbar_wait(uint32_t a, uint32_t parity) {
    asm volatile(
        "{\n\t.reg .pred P;\n\t"
        "WL_%=:\n\t"
        "mbarrier.try_wait.parity.acquire.cta.shared::cta.b64 P, [%0], %1, 0x989680;\n\t"
        "@P bra.uni WD_%=;\n\t"
        "bra.uni WL_%=;\n\t"
        "WD_%=:\n\t}"
        :: "r"(a), "r"(parity) : "memory");
}
static __device__ __forceinline__ void bulk_g2s(uint32_t dst, const void* src,
                                                uint32_t bytes, uint32_t mbar) {
    asm volatile(
        "cp.async.bulk.shared::cluster.global.mbarrier::complete_tx::bytes [%0], [%1], %2, [%3];"
        :: "r"(dst), "l"(src), "r"(bytes), "r"(mbar) : "memory");
}
static __device__ __forceinline__ void ldsm_x4(uint32_t& r0, uint32_t& r1,
                                               uint32_t& r2, uint32_t& r3, uint32_t a) {
    asm volatile("ldmatrix.sync.aligned.m8n8.x4.shared.b16 {%0,%1,%2,%3}, [%4];"
                 : "=r"(r0), "=r"(r1), "=r"(r2), "=r"(r3) : "r"(a));
}
static __device__ __forceinline__ void mma16816(float* d, const uint32_t* a,
                                                uint32_t b0, uint32_t b1) {
    asm volatile(
        "mma.sync.aligned.m16n8k16.row.col.f32.f16.f16.f32 "
        "{%0,%1,%2,%3}, {%4,%5,%6,%7}, {%8,%9}, {%0,%1,%2,%3};"
        : "+f"(d[0]), "+f"(d[1]), "+f"(d[2]), "+f"(d[3])
        : "r"(a[0]), "r"(a[1]), "r"(a[2]), "r"(a[3]), "r"(b0), "r"(b1));
}

// ---------------- packing kernels -------------------------------------------
__global__ void feat_kernel(const float* __restrict__ x) {
    int idx = blockIdx.x * blockDim.x + threadIdx.x;
    if (idx >= N_ROWS * I_DIM) return;
    int n = idx >> 11, i = idx & 2047;
    float v = clampf(x[idx]);
    float e = expf(2.0f * v);
    float t  = (e - 1.0f) / (e + 1.0f);
    float t2 = 2.0f * t * t  - 1.0f;
    float t3 = 2.0f * t * t2 - t;
    float t4 = 2.0f * t * t3 - t2;
    unsigned short h0 = __half_as_ushort(__float2half_rn(t));
    unsigned short h1 = __half_as_ushort(__float2half_rn(t2));
    unsigned short h2 = __half_as_ushort(__float2half_rn(t3));
    unsigned short h3 = __half_as_ushort(__float2half_rn(t4));
    uint2 u = make_uint2((uint32_t)h0 | ((uint32_t)h1 << 16),
                         (uint32_t)h2 | ((uint32_t)h3 << 16));
    uint32_t off = (uint32_t)(n & 127) * 128u + (uint32_t)(i & 15) * 8u;
    size_t base  = ((size_t)((n >> 7) * NPAIR + (i >> 4))) << 14;
    *reinterpret_cast<uint2*>(g_A + base + swz128(off)) = u;
}

__global__ void repackB_kernel(const float* __restrict__ coeffs) {
    int idx = blockIdx.x * blockDim.x + threadIdx.x;
    if (idx >= O_DIM * I_DIM) return;
    int o = idx >> 11, i = idx & 2047;
    const float* c5 = coeffs + (size_t)idx * 5;
    unsigned short h0 = __half_as_ushort(__float2half_rn(c5[1]));
    unsigned short h1 = __half_as_ushort(__float2half_rn(c5[2]));
    unsigned short h2 = __half_as_ushort(__float2half_rn(c5[3]));
    unsigned short h3 = __half_as_ushort(__float2half_rn(c5[4]));
    uint2 u = make_uint2((uint32_t)h0 | ((uint32_t)h1 << 16),
                         (uint32_t)h2 | ((uint32_t)h3 << 16));
    uint32_t off = (uint32_t)(o & 127) * 128u + (uint32_t)(i & 15) * 8u;
    size_t base  = ((size_t)((o >> 7) * NPAIR + (i >> 4))) << 14;
    *reinterpret_cast<uint2*>(g_B + base + swz128(off)) = u;
}

__global__ void bias_kernel(const float* __restrict__ coeffs) {
    int o = blockIdx.x;
    float s = 0.0f;
    for (int i = threadIdx.x; i < I_DIM; i += blockDim.x)
        s += coeffs[((size_t)o * I_DIM + i) * 5];
    __shared__ float red[256];
    red[threadIdx.x] = s;
    __syncthreads();
    for (int off = 128; off > 0; off >>= 1) {
        if (threadIdx.x < off) red[threadIdx.x] += red[threadIdx.x + off];
        __syncthreads();
    }
    if (threadIdx.x == 0) g_bias[o] = red[0];
}

// ---------------- GEMM: 128x128 CTA tile, 8 warps (4m x 2n), mma.sync -------
__global__ void __launch_bounds__(256, 2)
gemm_kernel(float* __restrict__ C) {
    extern __shared__ __align__(1024) unsigned char smem[];
    const uint32_t sb = smem_u32(smem);
    const uint32_t stage0 = sb + 1024;

    const int tid  = threadIdx.x;
    const int wid  = tid >> 5, lane = tid & 31;
    const int wm   = wid & 3;          // 0..3 -> 32-row slice of M tile
    const int wn   = wid >> 2;         // 0..1 -> 64-col slice of N tile
    const int mtile = blockIdx.y, ntile = blockIdx.x;

    // mbarrier init: full[s] at sb + s*8
    if (tid == 0) {
#pragma unroll
        for (int s = 0; s < NSTG; ++s) mbar_init(sb + s * 8, 1);
    }
    __syncthreads();

    const unsigned char* aSrc = g_A + ((size_t)mtile * NPAIR << 14);
    const unsigned char* bSrc = g_B + ((size_t)ntile * NPAIR << 14);

    if (tid == 0) {
#pragma unroll
        for (int p = 0; p < NSTG; ++p) {
            uint32_t fb = sb + p * 8;
            uint32_t dst = stage0 + p * STG_B;
            mbar_expect_tx(fb, STG_B);
            bulk_g2s(dst,          aSrc + ((size_t)p << 14), TILE_B, fb);
            bulk_g2s(dst + TILE_B, bSrc + ((size_t)p << 14), TILE_B, fb);
        }
    }

    float acc[2][8][4];
#pragma unroll
    for (int mi = 0; mi < 2; ++mi)
#pragma unroll
        for (int ni = 0; ni < 8; ++ni)
#pragma unroll
            for (int r = 0; r < 4; ++r) acc[mi][ni][r] = 0.0f;

    // ldmatrix address components (within stage, pre-swizzle offsets vary per ks)
    const int g = lane >> 3, r8 = lane & 7;
    // A: row = wm*32 + mi*16 + ((g&1)<<3) + r8 ; kbyte = ks*32 + ((g>>1)<<4)
    // B: row = wn*64 + nj*16 + ((g>>1)<<3) + r8 ; kbyte = ks*32 + ((g&1)<<4)
    const uint32_t aRow = (uint32_t)(wm * 32 + ((g & 1) << 3) + r8);
    const uint32_t bRow = (uint32_t)(wn * 64 + ((g >> 1) << 3) + r8);
    const uint32_t aKb  = (uint32_t)((g >> 1) << 4);
    const uint32_t bKb  = (uint32_t)((g & 1) << 4);

    for (int k = 0; k < NPAIR; ++k) {
        const int sp = k % NSTG;
        const uint32_t fb = sb + sp * 8;
        mbar_wait(fb, (uint32_t)((k / NSTG) & 1));

        const uint32_t stA = stage0 + sp * STG_B;
        const uint32_t stB = stA + TILE_B;

#pragma unroll
        for (int ks = 0; ks < 4; ++ks) {
            uint32_t a[2][4];
#pragma unroll
            for (int mi = 0; mi < 2; ++mi) {
                uint32_t off = (aRow + mi * 16) * 128u + (uint32_t)(ks * 32) + aKb;
                ldsm_x4(a[mi][0], a[mi][1], a[mi][2], a[mi][3], stA + swz128(off));
            }
            uint32_t b[4][4];
#pragma unroll
            for (int nj = 0; nj < 4; ++nj) {
                uint32_t off = (bRow + nj * 16) * 128u + (uint32_t)(ks * 32) + bKb;
                ldsm_x4(b[nj][0], b[nj][1], b[nj][2], b[nj][3], stB + swz128(off));
            }
#pragma unroll
            for (int mi = 0; mi < 2; ++mi)
#pragma unroll
                for (int ni = 0; ni < 8; ++ni)
                    mma16816(acc[mi][ni], a[mi],
                             b[ni >> 1][(ni & 1) * 2], b[ni >> 1][(ni & 1) * 2 + 1]);
        }

        __syncthreads();   // all warps done reading stage sp
        if (tid == 0 && k + NSTG < NPAIR) {
            const int kn = k + NSTG;
            uint32_t dst = stage0 + sp * STG_B;
            mbar_expect_tx(fb, STG_B);
            bulk_g2s(dst,          aSrc + ((size_t)kn << 14), TILE_B, fb);
            bulk_g2s(dst + TILE_B, bSrc + ((size_t)kn << 14), TILE_B, fb);
        }
    }

    // ---------------- epilogue: bias + clamp, float2 stores ------------------
    const int mBase = mtile * MT + wm * 32 + (lane >> 2);
    const int nBase = ntile * NT + wn * 64 + (lane & 3) * 2;

#pragma unroll
    for (int mi = 0; mi < 2; ++mi) {
#pragma unroll
        for (int ni = 0; ni < 8; ++ni) {
            const int n = nBase + ni * 8;
            const float b0 = g_bias[n], b1 = g_bias[n + 1];
            const int m0 = mBase + mi * 16;
            float2 v0, v1;
            v0.x = clampf(acc[mi][ni][0] + b0);
            v0.y = clampf(acc[mi][ni][1] + b1);
            v1.x = clampf(acc[mi][ni][2] + b0);
            v1.y = clampf(acc[mi][ni][3] + b1);
            *reinterpret_cast<float2*>(C + (size_t)m0 * O_DIM + n)       = v0;
            *reinterpret_cast<float2*>(C + (size_t)(m0 + 8) * O_DIM + n) = v1;
        }
    }
}

// ---------------------------------------------------------------------------
extern "C" void kernel_launch(void* const* d_in, const int* in_sizes, int n_in,
                              void* d_out, int out_size) {
    const float* x      = (const float*)d_in[0];
    const float* coeffs = (const float*)d_in[1];
    float* out          = (float*)d_out;

    cudaFuncSetAttribute(gemm_kernel, cudaFuncAttributeMaxDynamicSharedMemorySize, SMEM_TOTAL);

    feat_kernel   <<<(N_ROWS * I_DIM + 255) / 256, 256>>>(x);
    repackB_kernel<<<(O_DIM  * I_DIM + 255) / 256, 256>>>(coeffs);
    bias_kernel   <<<O_DIM, 256>>>(coeffs);
    gemm_kernel   <<<dim3(O_DIM / NT, N_ROWS / MT), 256, SMEM_TOTAL>>>(out);
}